// round 4
// baseline (speedup 1.0000x reference)
#include <cuda_runtime.h>

#define NN    2048
#define DIN   128
#define HH    256
#define DEMB  64
#define NSTRIP 4
#define STRIPJ (NN / NSTRIP)   // 512
#define BI    32
#define BJ    64

// -------- device scratch (no allocations allowed) --------
__device__ float g_emb[NN * DEMB];          // 512 KB
__device__ float g_sq[NN];                  // 8 KB
__device__ float g_xlast[NN * DIN];         // 1 MB
__device__ float g_ypart[NSTRIP * NN * DIN];// 4 MB
__device__ float g_degpart[NSTRIP * NN];    // 32 KB

__device__ __forceinline__ float sigmoidf(float z) {
    return 1.0f / (1.0f + __expf(-z));
}

// ============================================================
// Kernel A: out_x = relu(x@W0+b0); emb = relu(out_x@W1+b1);
//           sq = rowsum(emb^2); x_last = x@W2+b2
// One block = 16 rows, 256 threads.
// ============================================================
__global__ void __launch_bounds__(256) kA(
    const float* __restrict__ x,
    const float* __restrict__ W0, const float* __restrict__ b0,
    const float* __restrict__ W1, const float* __restrict__ b1,
    const float* __restrict__ W2, const float* __restrict__ b2)
{
    __shared__ float xs[16][DIN];        // 8 KB
    __shared__ float oxs[16][HH];        // 16 KB
    __shared__ float embs[16][DEMB + 1]; // padded vs bank conflicts

    const int t = threadIdx.x;
    const int row0 = blockIdx.x * 16;

    // load 16 x-rows
    #pragma unroll
    for (int idx = t; idx < 16 * DIN; idx += 256)
        xs[idx / DIN][idx % DIN] = x[row0 * DIN + idx];
    __syncthreads();

    // ---- stage 1: out_x tile [16, 256]; thread t owns column h=t ----
    {
        float acc[16];
        #pragma unroll
        for (int r = 0; r < 16; r++) acc[r] = 0.f;
        const int h = t;
        for (int k = 0; k < DIN; k++) {
            const float w = W0[k * HH + h];
            #pragma unroll
            for (int r = 0; r < 16; r++) acc[r] = fmaf(xs[r][k], w, acc[r]);
        }
        const float bb = b0[h];
        #pragma unroll
        for (int r = 0; r < 16; r++) oxs[r][h] = fmaxf(acc[r] + bb, 0.f);
    }
    __syncthreads();

    // ---- stage 2: emb tile [16, 64]; 4 row-groups x 64 columns ----
    {
        const int e  = t & 63;
        const int rg = t >> 6;             // 0..3 -> rows 4*rg..4*rg+3
        float acc[4] = {0.f, 0.f, 0.f, 0.f};
        for (int h = 0; h < HH; h++) {
            const float w = W1[h * DEMB + e];
            #pragma unroll
            for (int rr = 0; rr < 4; rr++)
                acc[rr] = fmaf(oxs[4 * rg + rr][h], w, acc[rr]);
        }
        const float bb = b1[e];
        #pragma unroll
        for (int rr = 0; rr < 4; rr++) {
            const float v = fmaxf(acc[rr] + bb, 0.f);
            embs[4 * rg + rr][e] = v;
            g_emb[(row0 + 4 * rg + rr) * DEMB + e] = v;
        }
    }

    // ---- stage 3: x_last tile [16, 128]; 2 row-groups x 128 columns ----
    {
        const int d  = t & 127;
        const int rg = t >> 7;             // 0..1 -> rows 8*rg..8*rg+7
        float acc[8];
        #pragma unroll
        for (int rr = 0; rr < 8; rr++) acc[rr] = 0.f;
        for (int k = 0; k < DIN; k++) {
            const float w = W2[k * DIN + d];
            #pragma unroll
            for (int rr = 0; rr < 8; rr++)
                acc[rr] = fmaf(xs[8 * rg + rr][k], w, acc[rr]);
        }
        const float bb = b2[d];
        #pragma unroll
        for (int rr = 0; rr < 8; rr++)
            g_xlast[(row0 + 8 * rg + rr) * DIN + d] = acc[rr] + bb;
    }
    __syncthreads();

    // ---- sq ----
    if (t < 16) {
        float s = 0.f;
        #pragma unroll
        for (int e = 0; e < DEMB; e++) { const float v = embs[t][e]; s = fmaf(v, v, s); }
        g_sq[row0 + t] = s;
    }
}

// ============================================================
// Kernel B: per block — 32 i-rows x 512 j-cols strip of A.
//  GEMM1: G = embI @ embJ^T   (k-major smem operands)
//  epilogue: A = sigmoid(c1*(2G - sqi - sqj) + c2) + eye -> adj_out
//  GEMM2: y += A_tile @ x_last_chunk   (register accumulators)
// Writes per-strip partials of deg and y (deterministic, no atomics).
// ============================================================
__global__ void __launch_bounds__(256) kB(
    const float* __restrict__ tempp,
    const float* __restrict__ thetap,
    float* __restrict__ adj_out)
{
    extern __shared__ float sm[];
    float* embIs = sm;                    // [64][33]  (k-major, padded)
    float* embJs = embIs + 64 * 33;       // [64][65]  (k-major, padded)
    float* xls   = embJs + 64 * 65;       // [64][128] (j-major)
    float* sqJs  = xls + 64 * DIN;        // [64]
    float* As    = sqJs + 64;             // [32][68]  (padded, 16B-alignable)
    float* degsh = As + 32 * 68;          // [32][16]

    const int t  = threadIdx.x;
    const int s  = blockIdx.x;            // strip
    const int i0 = blockIdx.y * BI;
    const int jstart = s * STRIPJ;

    const float c1 = 1.0f + *tempp;
    const float c2 = 5.0f + *thetap;

    // stage embI transposed (k-major)
    #pragma unroll
    for (int idx = t; idx < BI * DEMB; idx += 256) {
        const int k = idx & 63, r = idx >> 6;
        embIs[k * 33 + r] = g_emb[(i0 + r) * DEMB + k];
    }

    // GEMM1 thread coords: 2 rows x 4 cols
    const int c0 = (t & 15) * 4;
    const int r0 = (t >> 4) * 2;
    const float sqI0 = g_sq[i0 + r0];
    const float sqI1 = g_sq[i0 + r0 + 1];
    float degAcc0 = 0.f, degAcc1 = 0.f;

    // GEMM2 thread coords: 1 row x 16 cols
    const int yrow = t >> 3;
    const int ycol = (t & 7) * 16;
    float yacc[16];
    #pragma unroll
    for (int q = 0; q < 16; q++) yacc[q] = 0.f;

    for (int cj = 0; cj < STRIPJ / BJ; cj++) {
        const int jb = jstart + cj * BJ;
        __syncthreads();   // previous-iter readers done before overwrite

        // stage embJ transposed
        #pragma unroll
        for (int idx = t; idx < BJ * DEMB; idx += 256) {
            const int k = idx & 63, jl = idx >> 6;
            embJs[k * 65 + jl] = g_emb[(jb + jl) * DEMB + k];
        }
        if (t < BJ) sqJs[t] = g_sq[jb + t];
        // stage x_last chunk [64][128] via float4
        {
            const float4* src = (const float4*)(g_xlast + (size_t)jb * DIN);
            float4* dst = (float4*)xls;
            #pragma unroll
            for (int idx = t; idx < BJ * DIN / 4; idx += 256) dst[idx] = src[idx];
        }
        __syncthreads();

        // ---- GEMM1: G tile, 2x4 per thread over k=64 ----
        float a00 = 0.f, a01 = 0.f, a02 = 0.f, a03 = 0.f;
        float a10 = 0.f, a11 = 0.f, a12 = 0.f, a13 = 0.f;
        #pragma unroll 4
        for (int k = 0; k < DEMB; k++) {
            const float ai0 = embIs[k * 33 + r0];
            const float ai1 = embIs[k * 33 + r0 + 1];
            const float bj0 = embJs[k * 65 + c0 + 0];
            const float bj1 = embJs[k * 65 + c0 + 1];
            const float bj2 = embJs[k * 65 + c0 + 2];
            const float bj3 = embJs[k * 65 + c0 + 3];
            a00 = fmaf(ai0, bj0, a00); a01 = fmaf(ai0, bj1, a01);
            a02 = fmaf(ai0, bj2, a02); a03 = fmaf(ai0, bj3, a03);
            a10 = fmaf(ai1, bj0, a10); a11 = fmaf(ai1, bj1, a11);
            a12 = fmaf(ai1, bj2, a12); a13 = fmaf(ai1, bj3, a13);
        }

        // ---- epilogue: sigmoid + eye, write adj, stash A tile, deg ----
        {
            const float sj0 = sqJs[c0 + 0], sj1 = sqJs[c0 + 1];
            const float sj2 = sqJs[c0 + 2], sj3 = sqJs[c0 + 3];
            const int gi0 = i0 + r0;
            const int gj0 = jb + c0;

            float4 w0, w1;
            w0.x = sigmoidf(fmaf(c1, 2.f * a00 - sqI0 - sj0, c2));
            w0.y = sigmoidf(fmaf(c1, 2.f * a01 - sqI0 - sj1, c2));
            w0.z = sigmoidf(fmaf(c1, 2.f * a02 - sqI0 - sj2, c2));
            w0.w = sigmoidf(fmaf(c1, 2.f * a03 - sqI0 - sj3, c2));
            w1.x = sigmoidf(fmaf(c1, 2.f * a10 - sqI1 - sj0, c2));
            w1.y = sigmoidf(fmaf(c1, 2.f * a11 - sqI1 - sj1, c2));
            w1.z = sigmoidf(fmaf(c1, 2.f * a12 - sqI1 - sj2, c2));
            w1.w = sigmoidf(fmaf(c1, 2.f * a13 - sqI1 - sj3, c2));

            // identity on the diagonal
            const int d0 = gj0 - gi0;          // diag if col offset == 0..3
            if (d0 == 0)  w0.x += 1.f;
            if (d0 == -1) w0.y += 1.f;
            if (d0 == -2) w0.z += 1.f;
            if (d0 == -3) w0.w += 1.f;
            const int d1 = gj0 - (gi0 + 1);
            if (d1 == 0)  w1.x += 1.f;
            if (d1 == -1) w1.y += 1.f;
            if (d1 == -2) w1.z += 1.f;
            if (d1 == -3) w1.w += 1.f;

            degAcc0 += (w0.x + w0.y) + (w0.z + w0.w);
            degAcc1 += (w1.x + w1.y) + (w1.z + w1.w);

            *(float4*)(adj_out + (size_t)gi0 * NN + gj0)       = w0;
            *(float4*)(adj_out + (size_t)(gi0 + 1) * NN + gj0) = w1;

            *(float4*)(As + r0 * 68 + c0)       = w0;
            *(float4*)(As + (r0 + 1) * 68 + c0) = w1;
        }
        __syncthreads();

        // ---- GEMM2: y[32][128] += A[32][64] @ xls[64][128] ----
        for (int c = 0; c < BJ; c++) {
            const float a = As[yrow * 68 + c];
            const float4* xr = (const float4*)(xls + c * DIN + ycol);
            const float4 x0 = xr[0], x1 = xr[1], x2 = xr[2], x3 = xr[3];
            yacc[0]  = fmaf(a, x0.x, yacc[0]);  yacc[1]  = fmaf(a, x0.y, yacc[1]);
            yacc[2]  = fmaf(a, x0.z, yacc[2]);  yacc[3]  = fmaf(a, x0.w, yacc[3]);
            yacc[4]  = fmaf(a, x1.x, yacc[4]);  yacc[5]  = fmaf(a, x1.y, yacc[5]);
            yacc[6]  = fmaf(a, x1.z, yacc[6]);  yacc[7]  = fmaf(a, x1.w, yacc[7]);
            yacc[8]  = fmaf(a, x2.x, yacc[8]);  yacc[9]  = fmaf(a, x2.y, yacc[9]);
            yacc[10] = fmaf(a, x2.z, yacc[10]); yacc[11] = fmaf(a, x2.w, yacc[11]);
            yacc[12] = fmaf(a, x3.x, yacc[12]); yacc[13] = fmaf(a, x3.y, yacc[13]);
            yacc[14] = fmaf(a, x3.z, yacc[14]); yacc[15] = fmaf(a, x3.w, yacc[15]);
        }
    }

    // write y partials
    {
        float4* yp = (float4*)(g_ypart + ((size_t)s * NN + i0 + yrow) * DIN + ycol);
        yp[0] = make_float4(yacc[0],  yacc[1],  yacc[2],  yacc[3]);
        yp[1] = make_float4(yacc[4],  yacc[5],  yacc[6],  yacc[7]);
        yp[2] = make_float4(yacc[8],  yacc[9],  yacc[10], yacc[11]);
        yp[3] = make_float4(yacc[12], yacc[13], yacc[14], yacc[15]);
    }

    // deg reduction (deterministic)
    degsh[r0 * 16 + (t & 15)]       = degAcc0;
    degsh[(r0 + 1) * 16 + (t & 15)] = degAcc1;
    __syncthreads();
    if (t < BI) {
        float sdeg = 0.f;
        #pragma unroll
        for (int g = 0; g < 16; g++) sdeg += degsh[t * 16 + g];
        g_degpart[s * NN + i0 + t] = sdeg;
    }
}

// ============================================================
// Kernel C: out = relu( (sum_s y_part) / (sum_s deg_part) )
// ============================================================
__global__ void __launch_bounds__(256) kC(float* __restrict__ out)
{
    const int idx = blockIdx.x * 256 + threadIdx.x;  // < N*DIN
    const int i = idx >> 7;
    const int d = idx & 127;
    float deg = 0.f;
    #pragma unroll
    for (int s = 0; s < NSTRIP; s++) deg += g_degpart[s * NN + i];
    float y = 0.f;
    #pragma unroll
    for (int s = 0; s < NSTRIP; s++)
        y += g_ypart[((size_t)s * NN + i) * DIN + d];
    out[idx] = fmaxf(y / deg, 0.f);
}

// ============================================================
extern "C" void kernel_launch(void* const* d_in, const int* in_sizes, int n_in,
                              void* d_out, int out_size)
{
    const float* x     = (const float*)d_in[0];
    // d_in[1] = adj : unused (only its shape matters in the reference)
    const float* W0    = (const float*)d_in[2];
    const float* b0    = (const float*)d_in[3];
    const float* W1    = (const float*)d_in[4];
    const float* b1    = (const float*)d_in[5];
    const float* W2    = (const float*)d_in[6];
    const float* b2    = (const float*)d_in[7];
    const float* temp  = (const float*)d_in[8];
    const float* theta = (const float*)d_in[9];

    float* out     = (float*)d_out;          // [N, DIN] first
    float* adj_out = out + NN * DIN;         // then [N*N] adjacency

    kA<<<NN / 16, 256>>>(x, W0, b0, W1, b1, W2, b2);

    const int smemB = (64 * 33 + 64 * 65 + 64 * DIN + 64 + 32 * 68 + 32 * 16) * 4;
    cudaFuncSetAttribute(kB, cudaFuncAttributeMaxDynamicSharedMemorySize, smemB);
    dim3 gB(NSTRIP, NN / BI);
    kB<<<gB, 256, smemB>>>(temp, theta, adj_out);

    kC<<<NN * DIN / 256, 256>>>(out);
}

// round 5
// speedup vs baseline: 1.0014x; 1.0014x over previous
#include <cuda_runtime.h>

#define NN    2048
#define DIN   128
#define HH    256
#define DEMB  64
#define NSTRIP 4
#define STRIPJ (NN / NSTRIP)   // 512
#define BI    32
#define BJ    64

// -------- device scratch (no allocations allowed) --------
__device__ float g_emb[NN * DEMB];          // 512 KB
__device__ float g_sq[NN];                  // 8 KB
__device__ float g_xlast[NN * DIN];         // 1 MB
__device__ float g_ypart[NSTRIP * NN * DIN];// 4 MB
__device__ float g_degpart[NSTRIP * NN];    // 32 KB

__device__ __forceinline__ float sigmoidf(float z) {
    return 1.0f / (1.0f + __expf(-z));
}

// ============================================================
// Kernel A: out_x = relu(x@W0+b0); emb = relu(out_x@W1+b1);
//           sq = rowsum(emb^2); x_last = x@W2+b2
// One block = 16 rows, 256 threads.
// ============================================================
__global__ void __launch_bounds__(256) kA(
    const float* __restrict__ x,
    const float* __restrict__ W0, const float* __restrict__ b0,
    const float* __restrict__ W1, const float* __restrict__ b1,
    const float* __restrict__ W2, const float* __restrict__ b2)
{
    __shared__ float xs[16][DIN];        // 8 KB
    __shared__ float oxs[16][HH];        // 16 KB
    __shared__ float embs[16][DEMB + 1]; // padded vs bank conflicts

    const int t = threadIdx.x;
    const int row0 = blockIdx.x * 16;

    // load 16 x-rows
    #pragma unroll
    for (int idx = t; idx < 16 * DIN; idx += 256)
        xs[idx / DIN][idx % DIN] = x[row0 * DIN + idx];
    __syncthreads();

    // ---- stage 1: out_x tile [16, 256]; thread t owns column h=t ----
    {
        float acc[16];
        #pragma unroll
        for (int r = 0; r < 16; r++) acc[r] = 0.f;
        const int h = t;
        for (int k = 0; k < DIN; k++) {
            const float w = W0[k * HH + h];
            #pragma unroll
            for (int r = 0; r < 16; r++) acc[r] = fmaf(xs[r][k], w, acc[r]);
        }
        const float bb = b0[h];
        #pragma unroll
        for (int r = 0; r < 16; r++) oxs[r][h] = fmaxf(acc[r] + bb, 0.f);
    }
    __syncthreads();

    // ---- stage 2: emb tile [16, 64]; 4 row-groups x 64 columns ----
    {
        const int e  = t & 63;
        const int rg = t >> 6;             // 0..3 -> rows 4*rg..4*rg+3
        float acc[4] = {0.f, 0.f, 0.f, 0.f};
        for (int h = 0; h < HH; h++) {
            const float w = W1[h * DEMB + e];
            #pragma unroll
            for (int rr = 0; rr < 4; rr++)
                acc[rr] = fmaf(oxs[4 * rg + rr][h], w, acc[rr]);
        }
        const float bb = b1[e];
        #pragma unroll
        for (int rr = 0; rr < 4; rr++) {
            const float v = fmaxf(acc[rr] + bb, 0.f);
            embs[4 * rg + rr][e] = v;
            g_emb[(row0 + 4 * rg + rr) * DEMB + e] = v;
        }
    }

    // ---- stage 3: x_last tile [16, 128]; 2 row-groups x 128 columns ----
    {
        const int d  = t & 127;
        const int rg = t >> 7;             // 0..1 -> rows 8*rg..8*rg+7
        float acc[8];
        #pragma unroll
        for (int rr = 0; rr < 8; rr++) acc[rr] = 0.f;
        for (int k = 0; k < DIN; k++) {
            const float w = W2[k * DIN + d];
            #pragma unroll
            for (int rr = 0; rr < 8; rr++)
                acc[rr] = fmaf(xs[8 * rg + rr][k], w, acc[rr]);
        }
        const float bb = b2[d];
        #pragma unroll
        for (int rr = 0; rr < 8; rr++)
            g_xlast[(row0 + 8 * rg + rr) * DIN + d] = acc[rr] + bb;
    }
    __syncthreads();

    // ---- sq ----
    if (t < 16) {
        float s = 0.f;
        #pragma unroll
        for (int e = 0; e < DEMB; e++) { const float v = embs[t][e]; s = fmaf(v, v, s); }
        g_sq[row0 + t] = s;
    }
}

// ============================================================
// Kernel B: per block — 32 i-rows x 512 j-cols strip of A.
//  GEMM1: G = embI @ embJ^T   (k-major smem operands)
//  epilogue: A = sigmoid(c1*(2G - sqi - sqj) + c2) + eye -> adj_out
//  GEMM2: y += A_tile @ x_last_chunk   (register accumulators)
// Writes per-strip partials of deg and y (deterministic, no atomics).
// ============================================================
__global__ void __launch_bounds__(256) kB(
    const float* __restrict__ tempp,
    const float* __restrict__ thetap,
    float* __restrict__ adj_out)
{
    extern __shared__ float sm[];
    float* embIs = sm;                    // [64][33]  (k-major, padded)
    float* embJs = embIs + 64 * 33;       // [64][65]  (k-major, padded)
    float* xls   = embJs + 64 * 65;       // [64][128] (j-major)
    float* sqJs  = xls + 64 * DIN;        // [64]
    float* As    = sqJs + 64;             // [32][68]  (padded, 16B-alignable)
    float* degsh = As + 32 * 68;          // [32][16]

    const int t  = threadIdx.x;
    const int s  = blockIdx.x;            // strip
    const int i0 = blockIdx.y * BI;
    const int jstart = s * STRIPJ;

    const float c1 = 1.0f + *tempp;
    const float c2 = 5.0f + *thetap;

    // stage embI transposed (k-major)
    #pragma unroll
    for (int idx = t; idx < BI * DEMB; idx += 256) {
        const int k = idx & 63, r = idx >> 6;
        embIs[k * 33 + r] = g_emb[(i0 + r) * DEMB + k];
    }

    // GEMM1 thread coords: 2 rows x 4 cols
    const int c0 = (t & 15) * 4;
    const int r0 = (t >> 4) * 2;
    const float sqI0 = g_sq[i0 + r0];
    const float sqI1 = g_sq[i0 + r0 + 1];
    float degAcc0 = 0.f, degAcc1 = 0.f;

    // GEMM2 thread coords: 1 row x 16 cols
    const int yrow = t >> 3;
    const int ycol = (t & 7) * 16;
    float yacc[16];
    #pragma unroll
    for (int q = 0; q < 16; q++) yacc[q] = 0.f;

    for (int cj = 0; cj < STRIPJ / BJ; cj++) {
        const int jb = jstart + cj * BJ;
        __syncthreads();   // previous-iter readers done before overwrite

        // stage embJ transposed
        #pragma unroll
        for (int idx = t; idx < BJ * DEMB; idx += 256) {
            const int k = idx & 63, jl = idx >> 6;
            embJs[k * 65 + jl] = g_emb[(jb + jl) * DEMB + k];
        }
        if (t < BJ) sqJs[t] = g_sq[jb + t];
        // stage x_last chunk [64][128] via float4
        {
            const float4* src = (const float4*)(g_xlast + (size_t)jb * DIN);
            float4* dst = (float4*)xls;
            #pragma unroll
            for (int idx = t; idx < BJ * DIN / 4; idx += 256) dst[idx] = src[idx];
        }
        __syncthreads();

        // ---- GEMM1: G tile, 2x4 per thread over k=64 ----
        float a00 = 0.f, a01 = 0.f, a02 = 0.f, a03 = 0.f;
        float a10 = 0.f, a11 = 0.f, a12 = 0.f, a13 = 0.f;
        #pragma unroll 4
        for (int k = 0; k < DEMB; k++) {
            const float ai0 = embIs[k * 33 + r0];
            const float ai1 = embIs[k * 33 + r0 + 1];
            const float bj0 = embJs[k * 65 + c0 + 0];
            const float bj1 = embJs[k * 65 + c0 + 1];
            const float bj2 = embJs[k * 65 + c0 + 2];
            const float bj3 = embJs[k * 65 + c0 + 3];
            a00 = fmaf(ai0, bj0, a00); a01 = fmaf(ai0, bj1, a01);
            a02 = fmaf(ai0, bj2, a02); a03 = fmaf(ai0, bj3, a03);
            a10 = fmaf(ai1, bj0, a10); a11 = fmaf(ai1, bj1, a11);
            a12 = fmaf(ai1, bj2, a12); a13 = fmaf(ai1, bj3, a13);
        }

        // ---- epilogue: sigmoid + eye, write adj, stash A tile, deg ----
        {
            const float sj0 = sqJs[c0 + 0], sj1 = sqJs[c0 + 1];
            const float sj2 = sqJs[c0 + 2], sj3 = sqJs[c0 + 3];
            const int gi0 = i0 + r0;
            const int gj0 = jb + c0;

            float4 w0, w1;
            w0.x = sigmoidf(fmaf(c1, 2.f * a00 - sqI0 - sj0, c2));
            w0.y = sigmoidf(fmaf(c1, 2.f * a01 - sqI0 - sj1, c2));
            w0.z = sigmoidf(fmaf(c1, 2.f * a02 - sqI0 - sj2, c2));
            w0.w = sigmoidf(fmaf(c1, 2.f * a03 - sqI0 - sj3, c2));
            w1.x = sigmoidf(fmaf(c1, 2.f * a10 - sqI1 - sj0, c2));
            w1.y = sigmoidf(fmaf(c1, 2.f * a11 - sqI1 - sj1, c2));
            w1.z = sigmoidf(fmaf(c1, 2.f * a12 - sqI1 - sj2, c2));
            w1.w = sigmoidf(fmaf(c1, 2.f * a13 - sqI1 - sj3, c2));

            // identity on the diagonal
            const int d0 = gj0 - gi0;          // diag if col offset == 0..3
            if (d0 == 0)  w0.x += 1.f;
            if (d0 == -1) w0.y += 1.f;
            if (d0 == -2) w0.z += 1.f;
            if (d0 == -3) w0.w += 1.f;
            const int d1 = gj0 - (gi0 + 1);
            if (d1 == 0)  w1.x += 1.f;
            if (d1 == -1) w1.y += 1.f;
            if (d1 == -2) w1.z += 1.f;
            if (d1 == -3) w1.w += 1.f;

            degAcc0 += (w0.x + w0.y) + (w0.z + w0.w);
            degAcc1 += (w1.x + w1.y) + (w1.z + w1.w);

            *(float4*)(adj_out + (size_t)gi0 * NN + gj0)       = w0;
            *(float4*)(adj_out + (size_t)(gi0 + 1) * NN + gj0) = w1;

            *(float4*)(As + r0 * 68 + c0)       = w0;
            *(float4*)(As + (r0 + 1) * 68 + c0) = w1;
        }
        __syncthreads();

        // ---- GEMM2: y[32][128] += A[32][64] @ xls[64][128] ----
        for (int c = 0; c < BJ; c++) {
            const float a = As[yrow * 68 + c];
            const float4* xr = (const float4*)(xls + c * DIN + ycol);
            const float4 x0 = xr[0], x1 = xr[1], x2 = xr[2], x3 = xr[3];
            yacc[0]  = fmaf(a, x0.x, yacc[0]);  yacc[1]  = fmaf(a, x0.y, yacc[1]);
            yacc[2]  = fmaf(a, x0.z, yacc[2]);  yacc[3]  = fmaf(a, x0.w, yacc[3]);
            yacc[4]  = fmaf(a, x1.x, yacc[4]);  yacc[5]  = fmaf(a, x1.y, yacc[5]);
            yacc[6]  = fmaf(a, x1.z, yacc[6]);  yacc[7]  = fmaf(a, x1.w, yacc[7]);
            yacc[8]  = fmaf(a, x2.x, yacc[8]);  yacc[9]  = fmaf(a, x2.y, yacc[9]);
            yacc[10] = fmaf(a, x2.z, yacc[10]); yacc[11] = fmaf(a, x2.w, yacc[11]);
            yacc[12] = fmaf(a, x3.x, yacc[12]); yacc[13] = fmaf(a, x3.y, yacc[13]);
            yacc[14] = fmaf(a, x3.z, yacc[14]); yacc[15] = fmaf(a, x3.w, yacc[15]);
        }
    }

    // write y partials
    {
        float4* yp = (float4*)(g_ypart + ((size_t)s * NN + i0 + yrow) * DIN + ycol);
        yp[0] = make_float4(yacc[0],  yacc[1],  yacc[2],  yacc[3]);
        yp[1] = make_float4(yacc[4],  yacc[5],  yacc[6],  yacc[7]);
        yp[2] = make_float4(yacc[8],  yacc[9],  yacc[10], yacc[11]);
        yp[3] = make_float4(yacc[12], yacc[13], yacc[14], yacc[15]);
    }

    // deg reduction (deterministic)
    degsh[r0 * 16 + (t & 15)]       = degAcc0;
    degsh[(r0 + 1) * 16 + (t & 15)] = degAcc1;
    __syncthreads();
    if (t < BI) {
        float sdeg = 0.f;
        #pragma unroll
        for (int g = 0; g < 16; g++) sdeg += degsh[t * 16 + g];
        g_degpart[s * NN + i0 + t] = sdeg;
    }
}

// ============================================================
// Kernel C: out = relu( (sum_s y_part) / (sum_s deg_part) )
// ============================================================
__global__ void __launch_bounds__(256) kC(float* __restrict__ out)
{
    const int idx = blockIdx.x * 256 + threadIdx.x;  // < N*DIN
    const int i = idx >> 7;
    const int d = idx & 127;
    float deg = 0.f;
    #pragma unroll
    for (int s = 0; s < NSTRIP; s++) deg += g_degpart[s * NN + i];
    float y = 0.f;
    #pragma unroll
    for (int s = 0; s < NSTRIP; s++)
        y += g_ypart[((size_t)s * NN + i) * DIN + d];
    out[idx] = fmaxf(y / deg, 0.f);
}

// ============================================================
extern "C" void kernel_launch(void* const* d_in, const int* in_sizes, int n_in,
                              void* d_out, int out_size)
{
    const float* x     = (const float*)d_in[0];
    // d_in[1] = adj : unused (only its shape matters in the reference)
    const float* W0    = (const float*)d_in[2];
    const float* b0    = (const float*)d_in[3];
    const float* W1    = (const float*)d_in[4];
    const float* b1    = (const float*)d_in[5];
    const float* W2    = (const float*)d_in[6];
    const float* b2    = (const float*)d_in[7];
    const float* temp  = (const float*)d_in[8];
    const float* theta = (const float*)d_in[9];

    float* out     = (float*)d_out;          // [N, DIN] first
    float* adj_out = out + NN * DIN;         // then [N*N] adjacency

    kA<<<NN / 16, 256>>>(x, W0, b0, W1, b1, W2, b2);

    const int smemB = (64 * 33 + 64 * 65 + 64 * DIN + 64 + 32 * 68 + 32 * 16) * 4;
    cudaFuncSetAttribute(kB, cudaFuncAttributeMaxDynamicSharedMemorySize, smemB);
    dim3 gB(NSTRIP, NN / BI);
    kB<<<gB, 256, smemB>>>(temp, theta, adj_out);

    kC<<<NN * DIN / 256, 256>>>(out);
}

// round 6
// speedup vs baseline: 3.6419x; 3.6367x over previous
#include <cuda_runtime.h>

#define NN    2048
#define DIN   128
#define HH    256
#define DEMB  64
#define NSTRIP 8
#define STRIPJ (NN / NSTRIP)   // 256
#define BI    64
#define BJ    64
#define RA    8                // rows per kA block

// -------- device scratch (no allocations allowed) --------
__device__ __align__(16) float g_emb[NN * DEMB];            // 512 KB
__device__ __align__(16) float g_sq[NN];                    // 8 KB
__device__ __align__(16) float g_xlast[NN * DIN];           // 1 MB
__device__ __align__(16) float g_ypart[NSTRIP * NN * DIN];  // 8 MB
__device__ __align__(16) float g_degpart[NSTRIP * NN];      // 64 KB

// -------- packed fp32x2 helpers (exact fp32, 2 FMA / instr) --------
typedef unsigned long long ull;
__device__ __forceinline__ ull pk2(float a, float b) {
    ull r; asm("mov.b64 %0, {%1, %2};" : "=l"(r) : "f"(a), "f"(b)); return r;
}
__device__ __forceinline__ void fma2(ull& d, ull a, ull b) {
    asm("fma.rn.f32x2 %0, %1, %2, %0;" : "+l"(d) : "l"(a), "l"(b));
}
__device__ __forceinline__ float2 upk(ull v) {
    float2 f; asm("mov.b64 {%0, %1}, %2;" : "=f"(f.x), "=f"(f.y) : "l"(v)); return f;
}
__device__ __forceinline__ float sigmoidf(float z) {
    return 1.0f / (1.0f + __expf(-z));
}

// ============================================================
// Kernel A: out_x = relu(x@W0+b0); emb = relu(out_x@W1+b1);
//           sq = rowsum(emb^2); x_last = x@W2+b2
// 256 blocks x 8 rows, 256 threads. Transposed (k-major) staging
// so inner loops are  LDG(w) -> broadcast LDS.64 -> FFMA2.
// ============================================================
__global__ void __launch_bounds__(256) kA(
    const float* __restrict__ x,
    const float* __restrict__ W0, const float* __restrict__ b0,
    const float* __restrict__ W1, const float* __restrict__ b1,
    const float* __restrict__ W2, const float* __restrict__ b2)
{
    __shared__ float xsT[DIN][10];   // x rows transposed, pad 10 (even)
    __shared__ float oxT[HH][10];    // out_x transposed
    __shared__ float embS[RA][DEMB + 1];

    const int t = threadIdx.x;
    const int row0 = blockIdx.x * RA;

    // load x rows, transpose into xsT
    #pragma unroll
    for (int idx = t; idx < RA * DIN; idx += 256) {
        const int r = idx / DIN, k = idx % DIN;
        xsT[k][r] = x[row0 * DIN + idx];
    }
    __syncthreads();

    // ---- stage 1: out_x [8, 256]; thread t owns column h = t ----
    {
        ull acc[4] = {0, 0, 0, 0};
        const int h = t;
        #pragma unroll 4
        for (int k = 0; k < DIN; k++) {
            const float w = W0[k * HH + h];
            const ull ww = pk2(w, w);
            #pragma unroll
            for (int p = 0; p < 4; p++)
                fma2(acc[p], *(const ull*)&xsT[k][2 * p], ww);
        }
        const float bb = b0[h];
        #pragma unroll
        for (int p = 0; p < 4; p++) {
            const float2 v = upk(acc[p]);
            oxT[h][2 * p]     = fmaxf(v.x + bb, 0.f);
            oxT[h][2 * p + 1] = fmaxf(v.y + bb, 0.f);
        }
    }
    __syncthreads();

    // ---- stage 2: emb [8, 64]; thread: col e, row-pair 2rg ----
    {
        const int e  = t & 63;
        const int rg = t >> 6;          // 0..3 -> rows 2rg, 2rg+1
        ull acc = 0;
        #pragma unroll 4
        for (int hh = 0; hh < HH; hh++) {
            const float w = W1[hh * DEMB + e];
            fma2(acc, *(const ull*)&oxT[hh][2 * rg], pk2(w, w));
        }
        const float bb = b1[e];
        const float2 v = upk(acc);
        const float v0 = fmaxf(v.x + bb, 0.f);
        const float v1 = fmaxf(v.y + bb, 0.f);
        g_emb[(row0 + 2 * rg) * DEMB + e]     = v0;
        g_emb[(row0 + 2 * rg + 1) * DEMB + e] = v1;
        embS[2 * rg][e]     = v0;
        embS[2 * rg + 1][e] = v1;
    }

    // ---- stage 3: x_last [8, 128]; thread: col d, 4 rows ----
    {
        const int d  = t & 127;
        const int rg = t >> 7;          // 0..1 -> rows 4rg..4rg+3
        ull a0 = 0, a1 = 0;
        #pragma unroll 4
        for (int k = 0; k < DIN; k++) {
            const float w = W2[k * DIN + d];
            const ull ww = pk2(w, w);
            fma2(a0, *(const ull*)&xsT[k][4 * rg], ww);
            fma2(a1, *(const ull*)&xsT[k][4 * rg + 2], ww);
        }
        const float bb = b2[d];
        const float2 u = upk(a0), v = upk(a1);
        g_xlast[(row0 + 4 * rg) * DIN + d]     = u.x + bb;
        g_xlast[(row0 + 4 * rg + 1) * DIN + d] = u.y + bb;
        g_xlast[(row0 + 4 * rg + 2) * DIN + d] = v.x + bb;
        g_xlast[(row0 + 4 * rg + 3) * DIN + d] = v.y + bb;
    }
    __syncthreads();

    // ---- sq ----
    if (t < RA) {
        float s = 0.f;
        #pragma unroll
        for (int e = 0; e < DEMB; e++) { const float v = embS[t][e]; s = fmaf(v, v, s); }
        g_sq[row0 + t] = s;
    }
}

// ============================================================
// Kernel B: 64 i-rows x 256 j-cols strip of A per block.
//  GEMM1 (4x4/thread, FFMA2) -> sigmoid+eye epilogue -> adj +
//  GEMM2 (2 rows x 16 cols/thread, FFMA2, conflict-free cols).
// grid (8, 32) = 256 blocks, 2 blocks/SM target.
// ============================================================
__global__ void __launch_bounds__(256, 2) kB(
    const float* __restrict__ tempp,
    const float* __restrict__ thetap,
    float* __restrict__ adj_out)
{
    extern __shared__ float sm[];
    float* embIs = sm;                    // [64][68] k-major
    float* embJs = embIs + 64 * 68;       // [64][68] k-major
    float* xls   = embJs + 64 * 68;       // [64][132] j-major, padded
    float* As    = xls + 64 * 132;        // [64][68]
    float* sqJs  = As + 64 * 68;          // [64]
    float* degsh = sqJs + 64;             // [64][16]

    const int t  = threadIdx.x;
    const int s  = blockIdx.x;            // strip
    const int i0 = blockIdx.y * BI;
    const int jstart = s * STRIPJ;

    const float c1 = 1.0f + *tempp;
    const float c2 = 5.0f + *thetap;

    // stage embI transposed (k-major)
    #pragma unroll
    for (int idx = t; idx < BI * DEMB; idx += 256) {
        const int k = idx & 63, r = idx >> 6;
        embIs[k * 68 + r] = g_emb[(i0 + r) * DEMB + k];
    }

    // GEMM1 coords: 4 rows x 4 cols per thread
    const int r0 = (t >> 4) * 4;
    const int c0 = (t & 15) * 4;
    const float4 sqI = *(const float4*)&g_sq[i0 + r0];
    float degA[4] = {0.f, 0.f, 0.f, 0.f};

    // GEMM2 coords: rows {2q, 2q+1}, cols {g*4 + 32u + 0..3}
    const int q = t >> 3;
    const int g = t & 7;
    ull yac[2][8];
    #pragma unroll
    for (int r = 0; r < 2; r++)
        #pragma unroll
        for (int p = 0; p < 8; p++) yac[r][p] = 0ULL;

    for (int cj = 0; cj < STRIPJ / BJ; cj++) {
        const int jb = jstart + cj * BJ;
        __syncthreads();   // prev-iter readers done before overwrite

        // stage embJ transposed
        #pragma unroll
        for (int idx = t; idx < BJ * DEMB; idx += 256) {
            const int k = idx & 63, jl = idx >> 6;
            embJs[k * 68 + jl] = g_emb[(jb + jl) * DEMB + k];
        }
        if (t < BJ) sqJs[t] = g_sq[jb + t];
        // stage x_last chunk [64][132-padded] via float4
        {
            const float4* src = (const float4*)(g_xlast + (size_t)jb * DIN);
            #pragma unroll
            for (int idx = t; idx < BJ * DIN / 4; idx += 256) {
                const int row = idx >> 5, c4 = idx & 31;
                *(float4*)&xls[row * 132 + c4 * 4] = src[idx];
            }
        }
        __syncthreads();

        // ---- GEMM1: 4x4 per thread over k=64, packed j-pairs ----
        ull acc[4][2];
        #pragma unroll
        for (int r = 0; r < 4; r++) { acc[r][0] = 0ULL; acc[r][1] = 0ULL; }
        #pragma unroll 4
        for (int k = 0; k < DEMB; k++) {
            const float4 ai = *(const float4*)&embIs[k * 68 + r0];
            const float4 bj = *(const float4*)&embJs[k * 68 + c0];
            const ull b01 = pk2(bj.x, bj.y);
            const ull b23 = pk2(bj.z, bj.w);
            ull aa;
            aa = pk2(ai.x, ai.x); fma2(acc[0][0], aa, b01); fma2(acc[0][1], aa, b23);
            aa = pk2(ai.y, ai.y); fma2(acc[1][0], aa, b01); fma2(acc[1][1], aa, b23);
            aa = pk2(ai.z, ai.z); fma2(acc[2][0], aa, b01); fma2(acc[2][1], aa, b23);
            aa = pk2(ai.w, ai.w); fma2(acc[3][0], aa, b01); fma2(acc[3][1], aa, b23);
        }

        // ---- epilogue: sigmoid + eye, write adj, stash A tile, deg ----
        {
            const float4 sqJ = *(const float4*)&sqJs[c0];
            const int jbase = jb + c0;
            const float si[4] = {sqI.x, sqI.y, sqI.z, sqI.w};
            #pragma unroll
            for (int rr = 0; rr < 4; rr++) {
                const float2 g0 = upk(acc[rr][0]);
                const float2 g1 = upk(acc[rr][1]);
                const float zi = si[rr];
                const int i = i0 + r0 + rr;
                float4 w;
                w.x = sigmoidf(fmaf(c1, 2.f * g0.x - zi - sqJ.x, c2));
                w.y = sigmoidf(fmaf(c1, 2.f * g0.y - zi - sqJ.y, c2));
                w.z = sigmoidf(fmaf(c1, 2.f * g1.x - zi - sqJ.z, c2));
                w.w = sigmoidf(fmaf(c1, 2.f * g1.y - zi - sqJ.w, c2));
                if (i == jbase)     w.x += 1.f;
                if (i == jbase + 1) w.y += 1.f;
                if (i == jbase + 2) w.z += 1.f;
                if (i == jbase + 3) w.w += 1.f;
                degA[rr] += (w.x + w.y) + (w.z + w.w);
                *(float4*)(adj_out + (size_t)i * NN + jbase) = w;
                *(float4*)&As[(r0 + rr) * 68 + c0] = w;
            }
        }
        __syncthreads();

        // ---- GEMM2: y[64][128] += A[64][64] @ xls[64][128] ----
        #pragma unroll 4
        for (int c = 0; c < BJ; c++) {
            const float a0 = As[(2 * q) * 68 + c];
            const float a1 = As[(2 * q + 1) * 68 + c];
            const ull A0 = pk2(a0, a0);
            const ull A1 = pk2(a1, a1);
            #pragma unroll
            for (int u = 0; u < 4; u++) {
                const float4 xv = *(const float4*)&xls[c * 132 + g * 4 + 32 * u];
                const ull x01 = pk2(xv.x, xv.y);
                const ull x23 = pk2(xv.z, xv.w);
                fma2(yac[0][2 * u],     A0, x01);
                fma2(yac[0][2 * u + 1], A0, x23);
                fma2(yac[1][2 * u],     A1, x01);
                fma2(yac[1][2 * u + 1], A1, x23);
            }
        }
    }

    // write y partials
    #pragma unroll
    for (int r = 0; r < 2; r++) {
        float* base = g_ypart + ((size_t)s * NN + i0 + 2 * q + r) * DIN;
        #pragma unroll
        for (int u = 0; u < 4; u++) {
            const float2 p0 = upk(yac[r][2 * u]);
            const float2 p1 = upk(yac[r][2 * u + 1]);
            *(float4*)(base + g * 4 + 32 * u) = make_float4(p0.x, p0.y, p1.x, p1.y);
        }
    }

    // deg reduction (deterministic)
    #pragma unroll
    for (int rr = 0; rr < 4; rr++)
        degsh[(r0 + rr) * 16 + (t & 15)] = degA[rr];
    __syncthreads();
    if (t < BI) {
        float sdeg = 0.f;
        #pragma unroll
        for (int gg = 0; gg < 16; gg++) sdeg += degsh[t * 16 + gg];
        g_degpart[s * NN + i0 + t] = sdeg;
    }
}

// ============================================================
// Kernel C: out = relu( (sum_s y_part) / (sum_s deg_part) )
// ============================================================
__global__ void __launch_bounds__(256) kC(float* __restrict__ out)
{
    const int idx = blockIdx.x * 256 + threadIdx.x;  // < N*DIN
    const int i = idx >> 7;
    const int d = idx & 127;
    float deg = 0.f;
    #pragma unroll
    for (int s = 0; s < NSTRIP; s++) deg += g_degpart[s * NN + i];
    float y = 0.f;
    #pragma unroll
    for (int s = 0; s < NSTRIP; s++)
        y += g_ypart[((size_t)s * NN + i) * DIN + d];
    out[idx] = fmaxf(y / deg, 0.f);
}

// ============================================================
extern "C" void kernel_launch(void* const* d_in, const int* in_sizes, int n_in,
                              void* d_out, int out_size)
{
    const float* x     = (const float*)d_in[0];
    // d_in[1] = adj : unused (only its shape matters in the reference)
    const float* W0    = (const float*)d_in[2];
    const float* b0    = (const float*)d_in[3];
    const float* W1    = (const float*)d_in[4];
    const float* b1    = (const float*)d_in[5];
    const float* W2    = (const float*)d_in[6];
    const float* b2    = (const float*)d_in[7];
    const float* temp  = (const float*)d_in[8];
    const float* theta = (const float*)d_in[9];

    float* out     = (float*)d_out;          // [N, DIN] first
    float* adj_out = out + NN * DIN;         // then [N*N] adjacency

    kA<<<NN / RA, 256>>>(x, W0, b0, W1, b1, W2, b2);

    const int smemB = (64 * 68 + 64 * 68 + 64 * 132 + 64 * 68 + 64 + 64 * 16) * 4;
    cudaFuncSetAttribute(kB, cudaFuncAttributeMaxDynamicSharedMemorySize, smemB);
    dim3 gB(NSTRIP, NN / BI);
    kB<<<gB, 256, smemB>>>(temp, theta, adj_out);

    kC<<<NN * DIN / 256, 256>>>(out);
}

// round 7
// speedup vs baseline: 4.2119x; 1.1565x over previous
#include <cuda_runtime.h>

#define NN    2048
#define DIN   128
#define HH    256
#define DEMB  64
#define NSTRIP 8
#define STRIPJ (NN / NSTRIP)   // 256
#define BI    64
#define BJ    64
#define RA    16               // rows per kA block
#define XPAD  20               // xsT/oxT row pad (16B-aligned rows)

// -------- device scratch (no allocations allowed) --------
__device__ __align__(16) float g_emb[NN * DEMB];            // 512 KB
__device__ __align__(16) float g_sq[NN];                    // 8 KB
__device__ __align__(16) float g_xlast[NN * DIN];           // 1 MB
__device__ __align__(16) float g_ypart[NSTRIP * NN * DIN];  // 8 MB
__device__ __align__(16) float g_degpart[NSTRIP * NN];      // 64 KB

// -------- packed fp32x2 helpers (exact fp32, 2 FMA / instr) --------
typedef unsigned long long ull;
__device__ __forceinline__ ull pk2(float a, float b) {
    ull r; asm("mov.b64 %0, {%1, %2};" : "=l"(r) : "f"(a), "f"(b)); return r;
}
__device__ __forceinline__ void fma2(ull& d, ull a, ull b) {
    asm("fma.rn.f32x2 %0, %1, %2, %0;" : "+l"(d) : "l"(a), "l"(b));
}
__device__ __forceinline__ float2 upk(ull v) {
    float2 f; asm("mov.b64 {%0, %1}, %2;" : "=f"(f.x), "=f"(f.y) : "l"(v)); return f;
}
__device__ __forceinline__ float sigmoidf(float z) {
    return 1.0f / (1.0f + __expf(-z));
}

// ============================================================
// Kernel A: out_x = relu(x@W0+b0); emb = relu(out_x@W1+b1);
//           sq = rowsum(emb^2); x_last = x@W2+b2
// 128 blocks x 16 rows, 256 threads, single wave.
// Stages 1 and 3 share one k-loop (same x tile) with 16 weight
// LDGs in flight per thread -> L2-latency fully hidden.
// ============================================================
__global__ void __launch_bounds__(256) kA(
    const float* __restrict__ x,
    const float* __restrict__ W0, const float* __restrict__ b0,
    const float* __restrict__ W1, const float* __restrict__ b1,
    const float* __restrict__ W2, const float* __restrict__ b2)
{
    __shared__ float xsT[DIN][XPAD];   // x rows transposed (k-major)
    __shared__ float oxT[HH][XPAD];    // out_x transposed
    __shared__ float embS[RA][DEMB + 1];

    const int t = threadIdx.x;
    const int row0 = blockIdx.x * RA;

    // load x rows, transpose into xsT
    #pragma unroll
    for (int idx = t; idx < RA * DIN; idx += 256) {
        const int r = idx >> 7, k = idx & 127;
        xsT[k][r] = x[row0 * DIN + idx];
    }
    __syncthreads();

    // ---- merged stage 1 (out_x, col h = t) + stage 3 (x_last, col d) ----
    {
        const int h   = t;
        const int d   = t & 127;
        const int rg3 = t >> 7;                 // 0..1 -> rows 8rg3..8rg3+7
        ull acc1[8], acc3[4];
        #pragma unroll
        for (int p = 0; p < 8; p++) acc1[p] = 0ULL;
        #pragma unroll
        for (int p = 0; p < 4; p++) acc3[p] = 0ULL;

        #pragma unroll
        for (int kk = 0; kk < DIN; kk += 8) {
            float w0r[8], w2r[8];
            #pragma unroll
            for (int u = 0; u < 8; u++) {
                w0r[u] = W0[(kk + u) * HH + h];
                w2r[u] = W2[(kk + u) * DIN + d];
            }
            #pragma unroll
            for (int u = 0; u < 8; u++) {
                const int k = kk + u;
                const ull* xr = (const ull*)&xsT[k][0];   // 8 row-pairs
                const ull w0p = pk2(w0r[u], w0r[u]);
                #pragma unroll
                for (int p = 0; p < 8; p++) fma2(acc1[p], xr[p], w0p);
                const ull w2p = pk2(w2r[u], w2r[u]);
                #pragma unroll
                for (int p = 0; p < 4; p++) fma2(acc3[p], xr[4 * rg3 + p], w2p);
            }
        }

        const float bb0 = b0[h];
        #pragma unroll
        for (int p = 0; p < 8; p++) {
            const float2 v = upk(acc1[p]);
            oxT[h][2 * p]     = fmaxf(v.x + bb0, 0.f);
            oxT[h][2 * p + 1] = fmaxf(v.y + bb0, 0.f);
        }
        const float bb2 = b2[d];
        #pragma unroll
        for (int p = 0; p < 4; p++) {
            const float2 v = upk(acc3[p]);
            g_xlast[(row0 + 8 * rg3 + 2 * p) * DIN + d]     = v.x + bb2;
            g_xlast[(row0 + 8 * rg3 + 2 * p + 1) * DIN + d] = v.y + bb2;
        }
    }
    __syncthreads();

    // ---- stage 2: emb [16, 64]; thread: col e, rows 4rg..4rg+3 ----
    {
        const int e  = t & 63;
        const int rg = t >> 6;                  // 0..3
        ull acc2[2] = {0ULL, 0ULL};
        #pragma unroll
        for (int hh0 = 0; hh0 < HH; hh0 += 8) {
            float w1r[8];
            #pragma unroll
            for (int u = 0; u < 8; u++)
                w1r[u] = W1[(hh0 + u) * DEMB + e];
            #pragma unroll
            for (int u = 0; u < 8; u++) {
                const ull wp = pk2(w1r[u], w1r[u]);
                const ull* oxp = (const ull*)&oxT[hh0 + u][4 * rg];
                fma2(acc2[0], oxp[0], wp);
                fma2(acc2[1], oxp[1], wp);
            }
        }
        const float bb1 = b1[e];
        #pragma unroll
        for (int p = 0; p < 2; p++) {
            const float2 v = upk(acc2[p]);
            const float v0 = fmaxf(v.x + bb1, 0.f);
            const float v1 = fmaxf(v.y + bb1, 0.f);
            g_emb[(row0 + 4 * rg + 2 * p) * DEMB + e]     = v0;
            g_emb[(row0 + 4 * rg + 2 * p + 1) * DEMB + e] = v1;
            embS[4 * rg + 2 * p][e]     = v0;
            embS[4 * rg + 2 * p + 1][e] = v1;
        }
    }
    __syncthreads();

    // ---- sq ----
    if (t < RA) {
        float s = 0.f;
        #pragma unroll
        for (int e = 0; e < DEMB; e++) { const float v = embS[t][e]; s = fmaf(v, v, s); }
        g_sq[row0 + t] = s;
    }
}

// ============================================================
// Kernel B: 64 i-rows x 256 j-cols strip of A per block.
//  GEMM1 (4x4/thread, FFMA2) -> sigmoid+eye epilogue -> adj +
//  GEMM2 (2 rows x 16 cols/thread, FFMA2, conflict-free cols).
// grid (8, 32) = 256 blocks, 2 blocks/SM.
// ============================================================
__global__ void __launch_bounds__(256, 2) kB(
    const float* __restrict__ tempp,
    const float* __restrict__ thetap,
    float* __restrict__ adj_out)
{
    extern __shared__ float sm[];
    float* embIs = sm;                    // [64][68] k-major
    float* embJs = embIs + 64 * 68;       // [64][68] k-major
    float* xls   = embJs + 64 * 68;       // [64][132] j-major, padded
    float* As    = xls + 64 * 132;        // [64][68]
    float* sqJs  = As + 64 * 68;          // [64]
    float* degsh = sqJs + 64;             // [64][16]

    const int t  = threadIdx.x;
    const int s  = blockIdx.x;            // strip
    const int i0 = blockIdx.y * BI;
    const int jstart = s * STRIPJ;

    const float c1 = 1.0f + *tempp;
    const float c2 = 5.0f + *thetap;

    // stage embI transposed (k-major)
    #pragma unroll
    for (int idx = t; idx < BI * DEMB; idx += 256) {
        const int k = idx & 63, r = idx >> 6;
        embIs[k * 68 + r] = g_emb[(i0 + r) * DEMB + k];
    }

    // GEMM1 coords: 4 rows x 4 cols per thread
    const int r0 = (t >> 4) * 4;
    const int c0 = (t & 15) * 4;
    const float4 sqI = *(const float4*)&g_sq[i0 + r0];
    float degA[4] = {0.f, 0.f, 0.f, 0.f};

    // GEMM2 coords: rows {2q, 2q+1}, cols {g*4 + 32u + 0..3}
    const int q = t >> 3;
    const int g = t & 7;
    ull yac[2][8];
    #pragma unroll
    for (int r = 0; r < 2; r++)
        #pragma unroll
        for (int p = 0; p < 8; p++) yac[r][p] = 0ULL;

    for (int cj = 0; cj < STRIPJ / BJ; cj++) {
        const int jb = jstart + cj * BJ;
        __syncthreads();   // prev-iter readers done before overwrite

        // stage embJ transposed
        #pragma unroll
        for (int idx = t; idx < BJ * DEMB; idx += 256) {
            const int k = idx & 63, jl = idx >> 6;
            embJs[k * 68 + jl] = g_emb[(jb + jl) * DEMB + k];
        }
        if (t < BJ) sqJs[t] = g_sq[jb + t];
        // stage x_last chunk [64][132-padded] via float4
        {
            const float4* src = (const float4*)(g_xlast + (size_t)jb * DIN);
            #pragma unroll
            for (int idx = t; idx < BJ * DIN / 4; idx += 256) {
                const int row = idx >> 5, c4 = idx & 31;
                *(float4*)&xls[row * 132 + c4 * 4] = src[idx];
            }
        }
        __syncthreads();

        // ---- GEMM1: 4x4 per thread over k=64, packed j-pairs ----
        ull acc[4][2];
        #pragma unroll
        for (int r = 0; r < 4; r++) { acc[r][0] = 0ULL; acc[r][1] = 0ULL; }
        #pragma unroll 4
        for (int k = 0; k < DEMB; k++) {
            const float4 ai = *(const float4*)&embIs[k * 68 + r0];
            const float4 bj = *(const float4*)&embJs[k * 68 + c0];
            const ull b01 = pk2(bj.x, bj.y);
            const ull b23 = pk2(bj.z, bj.w);
            ull aa;
            aa = pk2(ai.x, ai.x); fma2(acc[0][0], aa, b01); fma2(acc[0][1], aa, b23);
            aa = pk2(ai.y, ai.y); fma2(acc[1][0], aa, b01); fma2(acc[1][1], aa, b23);
            aa = pk2(ai.z, ai.z); fma2(acc[2][0], aa, b01); fma2(acc[2][1], aa, b23);
            aa = pk2(ai.w, ai.w); fma2(acc[3][0], aa, b01); fma2(acc[3][1], aa, b23);
        }

        // ---- epilogue: sigmoid + eye, write adj, stash A tile, deg ----
        {
            const float4 sqJ = *(const float4*)&sqJs[c0];
            const int jbase = jb + c0;
            const float si[4] = {sqI.x, sqI.y, sqI.z, sqI.w};
            #pragma unroll
            for (int rr = 0; rr < 4; rr++) {
                const float2 g0 = upk(acc[rr][0]);
                const float2 g1 = upk(acc[rr][1]);
                const float zi = si[rr];
                const int i = i0 + r0 + rr;
                float4 w;
                w.x = sigmoidf(fmaf(c1, 2.f * g0.x - zi - sqJ.x, c2));
                w.y = sigmoidf(fmaf(c1, 2.f * g0.y - zi - sqJ.y, c2));
                w.z = sigmoidf(fmaf(c1, 2.f * g1.x - zi - sqJ.z, c2));
                w.w = sigmoidf(fmaf(c1, 2.f * g1.y - zi - sqJ.w, c2));
                if (i == jbase)     w.x += 1.f;
                if (i == jbase + 1) w.y += 1.f;
                if (i == jbase + 2) w.z += 1.f;
                if (i == jbase + 3) w.w += 1.f;
                degA[rr] += (w.x + w.y) + (w.z + w.w);
                *(float4*)(adj_out + (size_t)i * NN + jbase) = w;
                *(float4*)&As[(r0 + rr) * 68 + c0] = w;
            }
        }
        __syncthreads();

        // ---- GEMM2: y[64][128] += A[64][64] @ xls[64][128] ----
        #pragma unroll 4
        for (int c = 0; c < BJ; c++) {
            const float a0 = As[(2 * q) * 68 + c];
            const float a1 = As[(2 * q + 1) * 68 + c];
            const ull A0 = pk2(a0, a0);
            const ull A1 = pk2(a1, a1);
            #pragma unroll
            for (int u = 0; u < 4; u++) {
                const float4 xv = *(const float4*)&xls[c * 132 + g * 4 + 32 * u];
                const ull x01 = pk2(xv.x, xv.y);
                const ull x23 = pk2(xv.z, xv.w);
                fma2(yac[0][2 * u],     A0, x01);
                fma2(yac[0][2 * u + 1], A0, x23);
                fma2(yac[1][2 * u],     A1, x01);
                fma2(yac[1][2 * u + 1], A1, x23);
            }
        }
    }

    // write y partials
    #pragma unroll
    for (int r = 0; r < 2; r++) {
        float* base = g_ypart + ((size_t)s * NN + i0 + 2 * q + r) * DIN;
        #pragma unroll
        for (int u = 0; u < 4; u++) {
            const float2 p0 = upk(yac[r][2 * u]);
            const float2 p1 = upk(yac[r][2 * u + 1]);
            *(float4*)(base + g * 4 + 32 * u) = make_float4(p0.x, p0.y, p1.x, p1.y);
        }
    }

    // deg reduction (deterministic)
    #pragma unroll
    for (int rr = 0; rr < 4; rr++)
        degsh[(r0 + rr) * 16 + (t & 15)] = degA[rr];
    __syncthreads();
    if (t < BI) {
        float sdeg = 0.f;
        #pragma unroll
        for (int gg = 0; gg < 16; gg++) sdeg += degsh[t * 16 + gg];
        g_degpart[s * NN + i0 + t] = sdeg;
    }
}

// ============================================================
// Kernel C: out = relu( (sum_s y_part) / (sum_s deg_part) )
// ============================================================
__global__ void __launch_bounds__(256) kC(float* __restrict__ out)
{
    const int idx = blockIdx.x * 256 + threadIdx.x;  // < N*DIN
    const int i = idx >> 7;
    const int d = idx & 127;
    float deg = 0.f;
    #pragma unroll
    for (int s = 0; s < NSTRIP; s++) deg += g_degpart[s * NN + i];
    float y = 0.f;
    #pragma unroll
    for (int s = 0; s < NSTRIP; s++)
        y += g_ypart[((size_t)s * NN + i) * DIN + d];
    out[idx] = fmaxf(y / deg, 0.f);
}

// ============================================================
extern "C" void kernel_launch(void* const* d_in, const int* in_sizes, int n_in,
                              void* d_out, int out_size)
{
    const float* x     = (const float*)d_in[0];
    // d_in[1] = adj : unused (only its shape matters in the reference)
    const float* W0    = (const float*)d_in[2];
    const float* b0    = (const float*)d_in[3];
    const float* W1    = (const float*)d_in[4];
    const float* b1    = (const float*)d_in[5];
    const float* W2    = (const float*)d_in[6];
    const float* b2    = (const float*)d_in[7];
    const float* temp  = (const float*)d_in[8];
    const float* theta = (const float*)d_in[9];

    float* out     = (float*)d_out;          // [N, DIN] first
    float* adj_out = out + NN * DIN;         // then [N*N] adjacency

    kA<<<NN / RA, 256>>>(x, W0, b0, W1, b1, W2, b2);

    const int smemB = (64 * 68 + 64 * 68 + 64 * 132 + 64 * 68 + 64 + 64 * 16) * 4;
    cudaFuncSetAttribute(kB, cudaFuncAttributeMaxDynamicSharedMemorySize, smemB);
    dim3 gB(NSTRIP, NN / BI);
    kB<<<gB, 256, smemB>>>(temp, theta, adj_out);

    kC<<<NN * DIN / 256, 256>>>(out);
}

// round 8
// speedup vs baseline: 4.2236x; 1.0028x over previous
#include <cuda_runtime.h>

#define NN    2048
#define DIN   128
#define HH    256
#define DEMB  64
#define NSTRIP 8
#define STRIPJ (NN / NSTRIP)   // 256
#define BI    64
#define BJ    64
#define RA    16               // rows per kA block
#define XPAD  20               // xsT/oxT row pad (16B-aligned rows)

// -------- device scratch (no allocations allowed) --------
__device__ __align__(16) float g_emb[NN * DEMB];            // 512 KB
__device__ __align__(16) float g_sq[NN];                    // 8 KB
__device__ __align__(16) float g_xlast[NN * DIN];           // 1 MB
__device__ __align__(16) float g_ypart[NSTRIP * NN * DIN];  // 8 MB
__device__ __align__(16) float g_degpart[NSTRIP * NN];      // 64 KB

// -------- packed fp32x2 helpers (exact fp32, 2 FMA / instr) --------
typedef unsigned long long ull;
__device__ __forceinline__ ull pk2(float a, float b) {
    ull r; asm("mov.b64 %0, {%1, %2};" : "=l"(r) : "f"(a), "f"(b)); return r;
}
__device__ __forceinline__ void fma2(ull& d, ull a, ull b) {
    asm("fma.rn.f32x2 %0, %1, %2, %0;" : "+l"(d) : "l"(a), "l"(b));
}
__device__ __forceinline__ float2 upk(ull v) {
    float2 f; asm("mov.b64 {%0, %1}, %2;" : "=f"(f.x), "=f"(f.y) : "l"(v)); return f;
}
__device__ __forceinline__ float sigmoidf(float z) {
    return 1.0f / (1.0f + __expf(-z));
}

// ============================================================
// Kernel A: out_x = relu(x@W0+b0); emb = relu(out_x@W1+b1);
//           sq = rowsum(emb^2); x_last = x@W2+b2
// 128 blocks x 16 rows, 512 threads (16 warps/SM).
// Stage1+3 merged in one k-loop; W1 staged to smem during the
// stage1 latency shadow; stage2 k-split across thread halves.
// ============================================================
__global__ void __launch_bounds__(512) kA(
    const float* __restrict__ x,
    const float* __restrict__ W0, const float* __restrict__ b0,
    const float* __restrict__ W1, const float* __restrict__ b1,
    const float* __restrict__ W2, const float* __restrict__ b2)
{
    extern __shared__ float sma[];
    float* xsT  = sma;                   // [128][20]  x transposed
    float* oxT  = xsT + DIN * XPAD;      // [256][20]  out_x transposed
    float* W1s  = oxT + HH * XPAD;       // [256][64]
    float* embS = W1s + HH * DEMB;       // [16][65]
    float* red  = embS + RA * (DEMB+1);  // [4][64][4] stage2 partials

    const int t = threadIdx.x;
    const int row0 = blockIdx.x * RA;

    // load x rows transposed
    #pragma unroll
    for (int idx = t; idx < RA * DIN; idx += 512) {
        const int r = idx >> 7, k = idx & 127;
        xsT[k * XPAD + r] = x[row0 * DIN + idx];
    }
    // stage W1 -> smem (latency overlaps stage 1 below)
    {
        const float4* src = (const float4*)W1;
        float4* dst = (float4*)W1s;
        #pragma unroll
        for (int i = 0; i < (HH * DEMB / 4) / 512; i++)
            dst[t + 512 * i] = src[t + 512 * i];
    }
    __syncthreads();

    // ---- merged stage 1 (out_x) + stage 3 (x_last) ----
    {
        const int h    = t & 255;
        const int half = t >> 8;         // stage1 rows 8*half..8*half+7
        const int d    = t & 127;
        const int q    = t >> 7;         // stage3 rows 4*q..4*q+3
        ull acc1[4], acc3[2];
        #pragma unroll
        for (int p = 0; p < 4; p++) acc1[p] = 0ULL;
        acc3[0] = 0ULL; acc3[1] = 0ULL;

        #pragma unroll 2
        for (int kk = 0; kk < DIN; kk += 8) {
            float w0r[8], w2r[8];
            #pragma unroll
            for (int u = 0; u < 8; u++) {
                w0r[u] = W0[(kk + u) * HH + h];
                w2r[u] = W2[(kk + u) * DIN + d];
            }
            #pragma unroll
            for (int u = 0; u < 8; u++) {
                const float* xk = &xsT[(kk + u) * XPAD];
                const ull w0p = pk2(w0r[u], w0r[u]);
                const ull* xr1 = (const ull*)(xk + 8 * half);
                fma2(acc1[0], xr1[0], w0p);
                fma2(acc1[1], xr1[1], w0p);
                fma2(acc1[2], xr1[2], w0p);
                fma2(acc1[3], xr1[3], w0p);
                const ull w2p = pk2(w2r[u], w2r[u]);
                const ull* xr3 = (const ull*)(xk + 4 * q);
                fma2(acc3[0], xr3[0], w2p);
                fma2(acc3[1], xr3[1], w2p);
            }
        }

        const float bb0 = b0[h];
        #pragma unroll
        for (int p = 0; p < 4; p++) {
            const float2 v = upk(acc1[p]);
            oxT[h * XPAD + 8 * half + 2 * p]     = fmaxf(v.x + bb0, 0.f);
            oxT[h * XPAD + 8 * half + 2 * p + 1] = fmaxf(v.y + bb0, 0.f);
        }
        const float bb2 = b2[d];
        #pragma unroll
        for (int p = 0; p < 2; p++) {
            const float2 v = upk(acc3[p]);
            g_xlast[(row0 + 4 * q + 2 * p) * DIN + d]     = v.x + bb2;
            g_xlast[(row0 + 4 * q + 2 * p + 1) * DIN + d] = v.y + bb2;
        }
    }
    __syncthreads();

    // ---- stage 2: emb [16, 64]; e = t&63, rows 4rg..4rg+3,
    //      k-split: hh = t>>8 handles 128 of 256 h's ----
    {
        const int e  = t & 63;
        const int rg = (t >> 6) & 3;
        const int hh = t >> 8;
        const int h0 = hh * 128;
        ull acc[2] = {0ULL, 0ULL};
        #pragma unroll 8
        for (int h = h0; h < h0 + 128; h++) {
            const float w = W1s[h * DEMB + e];
            const ull wp = pk2(w, w);
            const ull* oxp = (const ull*)&oxT[h * XPAD + 4 * rg];
            fma2(acc[0], oxp[0], wp);
            fma2(acc[1], oxp[1], wp);
        }
        if (hh == 1) {
            const float2 a0 = upk(acc[0]), a1 = upk(acc[1]);
            *(float4*)&red[(rg * 64 + e) * 4] = make_float4(a0.x, a0.y, a1.x, a1.y);
        }
        __syncthreads();
        if (hh == 0) {
            const float4 rv = *(const float4*)&red[(rg * 64 + e) * 4];
            const float2 a0 = upk(acc[0]), a1 = upk(acc[1]);
            const float bb1 = b1[e];
            float v[4];
            v[0] = fmaxf(a0.x + rv.x + bb1, 0.f);
            v[1] = fmaxf(a0.y + rv.y + bb1, 0.f);
            v[2] = fmaxf(a1.x + rv.z + bb1, 0.f);
            v[3] = fmaxf(a1.y + rv.w + bb1, 0.f);
            #pragma unroll
            for (int p = 0; p < 4; p++) {
                g_emb[(row0 + 4 * rg + p) * DEMB + e] = v[p];
                embS[(4 * rg + p) * (DEMB + 1) + e] = v[p];
            }
        }
    }
    __syncthreads();

    // ---- sq ----
    if (t < RA) {
        float s = 0.f;
        #pragma unroll
        for (int e = 0; e < DEMB; e++) {
            const float v = embS[t * (DEMB + 1) + e];
            s = fmaf(v, v, s);
        }
        g_sq[row0 + t] = s;
    }
}

// ============================================================
// Kernel B: 64 i-rows x 256 j-cols strip of A per block.
//  GEMM1 (4x4/thread, FFMA2) -> sigmoid+eye epilogue -> adj +
//  GEMM2 (2 rows x 16 cols/thread, FFMA2, conflict-free cols).
// grid (8, 32) = 256 blocks, 2 blocks/SM.
// ============================================================
__global__ void __launch_bounds__(256, 2) kB(
    const float* __restrict__ tempp,
    const float* __restrict__ thetap,
    float* __restrict__ adj_out)
{
    extern __shared__ float sm[];
    float* embIs = sm;                    // [64][68] k-major
    float* embJs = embIs + 64 * 68;       // [64][68] k-major
    float* xls   = embJs + 64 * 68;       // [64][132] j-major, padded
    float* As    = xls + 64 * 132;        // [64][68]
    float* sqJs  = As + 64 * 68;          // [64]
    float* degsh = sqJs + 64;             // [64][16]

    const int t  = threadIdx.x;
    const int s  = blockIdx.x;            // strip
    const int i0 = blockIdx.y * BI;
    const int jstart = s * STRIPJ;

    const float c1 = 1.0f + *tempp;
    const float c2 = 5.0f + *thetap;

    // stage embI transposed (k-major)
    #pragma unroll
    for (int idx = t; idx < BI * DEMB; idx += 256) {
        const int k = idx & 63, r = idx >> 6;
        embIs[k * 68 + r] = g_emb[(i0 + r) * DEMB + k];
    }

    // GEMM1 coords: 4 rows x 4 cols per thread
    const int r0 = (t >> 4) * 4;
    const int c0 = (t & 15) * 4;
    const float4 sqI = *(const float4*)&g_sq[i0 + r0];
    float degA[4] = {0.f, 0.f, 0.f, 0.f};

    // GEMM2 coords: rows {2q, 2q+1}, cols {g*4 + 32u + 0..3}
    const int q = t >> 3;
    const int g = t & 7;
    ull yac[2][8];
    #pragma unroll
    for (int r = 0; r < 2; r++)
        #pragma unroll
        for (int p = 0; p < 8; p++) yac[r][p] = 0ULL;

    for (int cj = 0; cj < STRIPJ / BJ; cj++) {
        const int jb = jstart + cj * BJ;
        __syncthreads();   // prev-iter readers done before overwrite

        // stage embJ transposed
        #pragma unroll
        for (int idx = t; idx < BJ * DEMB; idx += 256) {
            const int k = idx & 63, jl = idx >> 6;
            embJs[k * 68 + jl] = g_emb[(jb + jl) * DEMB + k];
        }
        if (t < BJ) sqJs[t] = g_sq[jb + t];
        // stage x_last chunk [64][132-padded] via float4
        {
            const float4* src = (const float4*)(g_xlast + (size_t)jb * DIN);
            #pragma unroll
            for (int idx = t; idx < BJ * DIN / 4; idx += 256) {
                const int row = idx >> 5, c4 = idx & 31;
                *(float4*)&xls[row * 132 + c4 * 4] = src[idx];
            }
        }
        __syncthreads();

        // ---- GEMM1: 4x4 per thread over k=64, packed j-pairs ----
        ull acc[4][2];
        #pragma unroll
        for (int r = 0; r < 4; r++) { acc[r][0] = 0ULL; acc[r][1] = 0ULL; }
        #pragma unroll 4
        for (int k = 0; k < DEMB; k++) {
            const float4 ai = *(const float4*)&embIs[k * 68 + r0];
            const float4 bj = *(const float4*)&embJs[k * 68 + c0];
            const ull b01 = pk2(bj.x, bj.y);
            const ull b23 = pk2(bj.z, bj.w);
            ull aa;
            aa = pk2(ai.x, ai.x); fma2(acc[0][0], aa, b01); fma2(acc[0][1], aa, b23);
            aa = pk2(ai.y, ai.y); fma2(acc[1][0], aa, b01); fma2(acc[1][1], aa, b23);
            aa = pk2(ai.z, ai.z); fma2(acc[2][0], aa, b01); fma2(acc[2][1], aa, b23);
            aa = pk2(ai.w, ai.w); fma2(acc[3][0], aa, b01); fma2(acc[3][1], aa, b23);
        }

        // ---- epilogue: sigmoid + eye, write adj, stash A tile, deg ----
        {
            const float4 sqJ = *(const float4*)&sqJs[c0];
            const int jbase = jb + c0;
            const float si[4] = {sqI.x, sqI.y, sqI.z, sqI.w};
            #pragma unroll
            for (int rr = 0; rr < 4; rr++) {
                const float2 g0 = upk(acc[rr][0]);
                const float2 g1 = upk(acc[rr][1]);
                const float zi = si[rr];
                const int i = i0 + r0 + rr;
                float4 w;
                w.x = sigmoidf(fmaf(c1, 2.f * g0.x - zi - sqJ.x, c2));
                w.y = sigmoidf(fmaf(c1, 2.f * g0.y - zi - sqJ.y, c2));
                w.z = sigmoidf(fmaf(c1, 2.f * g1.x - zi - sqJ.z, c2));
                w.w = sigmoidf(fmaf(c1, 2.f * g1.y - zi - sqJ.w, c2));
                if (i == jbase)     w.x += 1.f;
                if (i == jbase + 1) w.y += 1.f;
                if (i == jbase + 2) w.z += 1.f;
                if (i == jbase + 3) w.w += 1.f;
                degA[rr] += (w.x + w.y) + (w.z + w.w);
                *(float4*)(adj_out + (size_t)i * NN + jbase) = w;
                *(float4*)&As[(r0 + rr) * 68 + c0] = w;
            }
        }
        __syncthreads();

        // ---- GEMM2: y[64][128] += A[64][64] @ xls[64][128] ----
        #pragma unroll 4
        for (int c = 0; c < BJ; c++) {
            const float a0 = As[(2 * q) * 68 + c];
            const float a1 = As[(2 * q + 1) * 68 + c];
            const ull A0 = pk2(a0, a0);
            const ull A1 = pk2(a1, a1);
            #pragma unroll
            for (int u = 0; u < 4; u++) {
                const float4 xv = *(const float4*)&xls[c * 132 + g * 4 + 32 * u];
                const ull x01 = pk2(xv.x, xv.y);
                const ull x23 = pk2(xv.z, xv.w);
                fma2(yac[0][2 * u],     A0, x01);
                fma2(yac[0][2 * u + 1], A0, x23);
                fma2(yac[1][2 * u],     A1, x01);
                fma2(yac[1][2 * u + 1], A1, x23);
            }
        }
    }

    // write y partials
    #pragma unroll
    for (int r = 0; r < 2; r++) {
        float* base = g_ypart + ((size_t)s * NN + i0 + 2 * q + r) * DIN;
        #pragma unroll
        for (int u = 0; u < 4; u++) {
            const float2 p0 = upk(yac[r][2 * u]);
            const float2 p1 = upk(yac[r][2 * u + 1]);
            *(float4*)(base + g * 4 + 32 * u) = make_float4(p0.x, p0.y, p1.x, p1.y);
        }
    }

    // deg reduction (deterministic)
    #pragma unroll
    for (int rr = 0; rr < 4; rr++)
        degsh[(r0 + rr) * 16 + (t & 15)] = degA[rr];
    __syncthreads();
    if (t < BI) {
        float sdeg = 0.f;
        #pragma unroll
        for (int gg = 0; gg < 16; gg++) sdeg += degsh[t * 16 + gg];
        g_degpart[s * NN + i0 + t] = sdeg;
    }
}

// ============================================================
// Kernel C: out = relu( (sum_s y_part) / (sum_s deg_part) )
// ============================================================
__global__ void __launch_bounds__(256) kC(float* __restrict__ out)
{
    const int idx = blockIdx.x * 256 + threadIdx.x;  // < N*DIN
    const int i = idx >> 7;
    const int d = idx & 127;
    float deg = 0.f;
    #pragma unroll
    for (int s = 0; s < NSTRIP; s++) deg += g_degpart[s * NN + i];
    float y = 0.f;
    #pragma unroll
    for (int s = 0; s < NSTRIP; s++)
        y += g_ypart[((size_t)s * NN + i) * DIN + d];
    out[idx] = fmaxf(y / deg, 0.f);
}

// ============================================================
extern "C" void kernel_launch(void* const* d_in, const int* in_sizes, int n_in,
                              void* d_out, int out_size)
{
    const float* x     = (const float*)d_in[0];
    // d_in[1] = adj : unused (only its shape matters in the reference)
    const float* W0    = (const float*)d_in[2];
    const float* b0    = (const float*)d_in[3];
    const float* W1    = (const float*)d_in[4];
    const float* b1    = (const float*)d_in[5];
    const float* W2    = (const float*)d_in[6];
    const float* b2    = (const float*)d_in[7];
    const float* temp  = (const float*)d_in[8];
    const float* theta = (const float*)d_in[9];

    float* out     = (float*)d_out;          // [N, DIN] first
    float* adj_out = out + NN * DIN;         // then [N*N] adjacency

    const int smemA = (DIN * XPAD + HH * XPAD + HH * DEMB
                       + RA * (DEMB + 1) + 4 * 64 * 4) * 4;
    cudaFuncSetAttribute(kA, cudaFuncAttributeMaxDynamicSharedMemorySize, smemA);
    kA<<<NN / RA, 512, smemA>>>(x, W0, b0, W1, b1, W2, b2);

    const int smemB = (64 * 68 + 64 * 68 + 64 * 132 + 64 * 68 + 64 + 64 * 16) * 4;
    cudaFuncSetAttribute(kB, cudaFuncAttributeMaxDynamicSharedMemorySize, smemB);
    dim3 gB(NSTRIP, NN / BI);
    kB<<<gB, 256, smemB>>>(temp, theta, adj_out);

    kC<<<NN * DIN / 256, 256>>>(out);
}